// round 1
// baseline (speedup 1.0000x reference)
#include <cuda_runtime.h>

#define C 128
#define NMAX 32768
#define EMAX 524288
#define BMAX 64
#define KORDER 4
#define BETA 0.5f

// ---------------- scratch (static device memory, no allocation) ----------------
__device__ __align__(256) float g_q[NMAX * C];
__device__ __align__(256) float g_k[NMAX * C];
__device__ __align__(256) float g_cur0[NMAX * C];
__device__ __align__(256) float g_cur1[NMAX * C];
__device__ __align__(256) float g_acc[NMAX * C];
__device__ __align__(256) float g_deg[NMAX];
__device__ __align__(256) float g_dinv[NMAX];
__device__ __align__(256) float g_coef[EMAX];
__device__ __align__(256) int   g_cnt[NMAX];
__device__ __align__(256) int   g_rowptr[NMAX + 1];
__device__ __align__(256) int   g_fill[NMAX];
__device__ __align__(256) int   g_ccol[EMAX];
__device__ __align__(256) float g_ccoef[EMAX];
__device__ __align__(256) int   g_offsets[BMAX + 1];
__device__ __align__(256) int   g_batch[NMAX];
__device__ __align__(256) float g_Mp[BMAX * 4 * C * C];   // 4 partial K^T V per graph
__device__ __align__(256) float g_ksum[BMAX * C];
__device__ __align__(256) float g_vsum[BMAX * C];
__device__ __align__(256) float g_denom[NMAX];

// ---------------- preprocessing ----------------
__global__ void k_zero(int N) {
    int i = blockIdx.x * blockDim.x + threadIdx.x;
    if (i < N) { g_deg[i] = 0.f; g_cnt[i] = 0; g_fill[i] = 0; }
}

__global__ void k_offsets(const int* __restrict__ nn, int B) {
    if (threadIdx.x == 0) {
        int run = 0;
        for (int b = 0; b < B; b++) { g_offsets[b] = run; run += nn[b]; }
        g_offsets[B] = run;
    }
}

__global__ void k_batch(int N, int B) {
    __shared__ int offs[BMAX + 1];
    for (int i = threadIdx.x; i <= B; i += blockDim.x) offs[i] = g_offsets[i];
    __syncthreads();
    int n = blockIdx.x * blockDim.x + threadIdx.x;
    if (n >= N) return;
    int lo = 0, hi = B - 1;
    while (lo < hi) {
        int mid = (lo + hi + 1) >> 1;
        if (offs[mid] <= n) lo = mid; else hi = mid - 1;
    }
    g_batch[n] = lo;
}

__global__ void k_deg(const int* __restrict__ row, const float* __restrict__ w, int E) {
    int e = blockIdx.x * blockDim.x + threadIdx.x;
    if (e < E) atomicAdd(&g_deg[row[e]], w[e]);
}

__global__ void k_dinv(int N) {
    int n = blockIdx.x * blockDim.x + threadIdx.x;
    if (n < N) {
        float d = g_deg[n];
        g_dinv[n] = (d > 0.f) ? (1.f / sqrtf(d)) : 0.f;
    }
}

__global__ void k_coef(const int* __restrict__ row, const int* __restrict__ col,
                       const float* __restrict__ w, int E) {
    int e = blockIdx.x * blockDim.x + threadIdx.x;
    if (e < E) {
        int r = row[e];
        g_coef[e] = g_dinv[r] * g_dinv[col[e]] * w[e];
        atomicAdd(&g_cnt[r], 1);
    }
}

__global__ void k_scan(int N) {
    __shared__ int sm[1024];
    int t = threadIdx.x;
    int per = (N + 1023) >> 10;
    int base = t * per;
    int s = 0;
    for (int i = 0; i < per; i++) { int idx = base + i; if (idx < N) s += g_cnt[idx]; }
    sm[t] = s;
    __syncthreads();
    for (int off = 1; off < 1024; off <<= 1) {
        int v = (t >= off) ? sm[t - off] : 0;
        __syncthreads();
        sm[t] += v;
        __syncthreads();
    }
    int run = (t == 0) ? 0 : sm[t - 1];
    for (int i = 0; i < per; i++) {
        int idx = base + i;
        if (idx < N) { g_rowptr[idx] = run; run += g_cnt[idx]; }
    }
    if (t == 1023) g_rowptr[N] = run;
}

__global__ void k_scatter(const int* __restrict__ row, const int* __restrict__ col, int E) {
    int e = blockIdx.x * blockDim.x + threadIdx.x;
    if (e < E) {
        int r = row[e];
        int p = g_rowptr[r] + atomicAdd(&g_fill[r], 1);
        g_ccol[p] = col[e];
        g_ccoef[p] = g_coef[e];
    }
}

// ---------------- dense GEMM: out[m][c] = sum_i A[m][i] * W[c][i] + bias[c] ----------------
// 64 nodes / block, 256 threads, float4 register tiles (8 nodes x 4 channels / thread)
__global__ __launch_bounds__(256) void k_gemm_bias(
    const float* __restrict__ Ain, const float* __restrict__ W,
    const float* __restrict__ bias, float* __restrict__ Oout, int mode, int N)
{
    extern __shared__ float sm[];
    float* Wt = sm;                  // [128][132] transposed W
    float* Xs = Wt + 128 * 132;      // [64][128]
    float* bs = Xs + 64 * C;         // [128]
    const float* A = (mode == 2) ? g_acc : Ain;
    float* out = (mode == 0) ? g_q : ((mode == 1) ? g_k : Oout);
    int tid = threadIdx.x;
    for (int idx = tid; idx < C * C; idx += 256) {
        int c = idx >> 7, i = idx & 127;
        Wt[i * 132 + c] = W[idx];
    }
    if (tid < C) bs[tid] = bias[tid];
    int nb = blockIdx.x * 64;
    const float4* Ax = (const float4*)(A + (size_t)nb * C);
    float4* Xs4 = (float4*)Xs;
    for (int q = tid; q < 64 * C / 4; q += 256) Xs4[q] = Ax[q];
    __syncthreads();

    int c4 = tid & 31, mg = tid >> 5;
    float4 bl = ((const float4*)bs)[c4];
    float4 accv[8];
#pragma unroll
    for (int j = 0; j < 8; j++) accv[j] = bl;
    const float* xbase = Xs + mg * 8 * C;
#pragma unroll 2
    for (int i = 0; i < C; i++) {
        float4 w = *(const float4*)&Wt[i * 132 + c4 * 4];
#pragma unroll
        for (int j = 0; j < 8; j++) {
            float xv = xbase[j * C + i];
            accv[j].x = fmaf(xv, w.x, accv[j].x);
            accv[j].y = fmaf(xv, w.y, accv[j].y);
            accv[j].z = fmaf(xv, w.z, accv[j].z);
            accv[j].w = fmaf(xv, w.w, accv[j].w);
        }
    }
#pragma unroll
    for (int j = 0; j < 8; j++) {
        int m = nb + mg * 8 + j;
        ((float4*)(out + (size_t)m * C))[c4] = accv[j];
    }
}

// ---------------- row L2-normalize (warp per node) ----------------
__global__ void k_norm(int sel, int N) {
    float* v = sel ? g_k : g_q;
    int w = (blockIdx.x * blockDim.x + threadIdx.x) >> 5;
    int lane = threadIdx.x & 31;
    if (w >= N) return;
    float4 x = ((const float4*)(v + (size_t)w * C))[lane];
    float s = x.x * x.x + x.y * x.y + x.z * x.z + x.w * x.w;
#pragma unroll
    for (int o = 16; o; o >>= 1) s += __shfl_xor_sync(0xffffffffu, s, o);
    float inv = 1.f / sqrtf(s);
    x.x *= inv; x.y *= inv; x.z *= inv; x.w *= inv;
    ((float4*)(v + (size_t)w * C))[lane] = x;
}

// ---------------- per-graph column sums (ksum once, vsum per iter) ----------------
__global__ void k_colsum(int mode, int flip) {
    int b = blockIdx.x, t = threadIdx.x;   // 128 threads
    const float* src = (mode == 0) ? g_k : (flip ? g_cur1 : g_cur0);
    float* out = (mode == 0) ? g_ksum : g_vsum;
    int s0 = g_offsets[b], s1 = g_offsets[b + 1];
    float s = 0.f;
    for (int n = s0; n < s1; n++) s += src[(size_t)n * C + t];
    out[b * C + t] = s;
}

// ---------------- denom[n] = q[n]·ksum[b] + n_b  (warp per node, once) ----------------
__global__ void k_denom(int N) {
    int w = (blockIdx.x * blockDim.x + threadIdx.x) >> 5;
    int lane = threadIdx.x & 31;
    if (w >= N) return;
    int b = g_batch[w];
    float4 q = ((const float4*)(g_q + (size_t)w * C))[lane];
    float4 kk = ((const float4*)(g_ksum + b * C))[lane];
    float s = q.x * kk.x + q.y * kk.y + q.z * kk.z + q.w * kk.w;
#pragma unroll
    for (int o = 16; o; o >>= 1) s += __shfl_xor_sync(0xffffffffu, s, o);
    if (lane == 0) g_denom[w] = s + (float)(g_offsets[b + 1] - g_offsets[b]);
}

__global__ void k_init(const float* __restrict__ x, int total4) {
    int i = blockIdx.x * blockDim.x + threadIdx.x;
    if (i < total4) {
        float4 v = ((const float4*)x)[i];
        ((float4*)g_cur0)[i] = v;
        ((float4*)g_acc)[i] = v;
    }
}

// ---------------- M_b partial build: 4 blocks/graph, 8x8 register tiles ----------------
__global__ __launch_bounds__(256) void k_mbuild(int flip) {
    __shared__ __align__(16) float ks[C];
    __shared__ __align__(16) float vs_[C];
    const float* src = flip ? g_cur1 : g_cur0;
    int b = blockIdx.x >> 2, p = blockIdx.x & 3;
    int s0 = g_offsets[b], s1 = g_offsets[b + 1];
    int nb = s1 - s0;
    int chunk = (nb + 3) >> 2;
    int n0 = s0 + p * chunk;
    int n1 = min(n0 + chunk, s1);
    int tid = threadIdx.x;
    int ti = tid >> 4, tj = tid & 15;
    float r[8][8];
#pragma unroll
    for (int a = 0; a < 8; a++)
#pragma unroll
        for (int c = 0; c < 8; c++) r[a][c] = 0.f;

    for (int n = n0; n < n1; n++) {
        __syncthreads();
        if (tid < C) ks[tid] = g_k[(size_t)n * C + tid];
        else         vs_[tid - C] = src[(size_t)n * C + tid - C];
        __syncthreads();
        float4 k0 = ((const float4*)ks)[ti * 2];
        float4 k1 = ((const float4*)ks)[ti * 2 + 1];
        float4 v0 = ((const float4*)vs_)[tj * 2];
        float4 v1 = ((const float4*)vs_)[tj * 2 + 1];
        float ka[8] = {k0.x, k0.y, k0.z, k0.w, k1.x, k1.y, k1.z, k1.w};
        float va[8] = {v0.x, v0.y, v0.z, v0.w, v1.x, v1.y, v1.z, v1.w};
#pragma unroll
        for (int a = 0; a < 8; a++)
#pragma unroll
            for (int c = 0; c < 8; c++) r[a][c] = fmaf(ka[a], va[c], r[a][c]);
    }
    float* out = g_Mp + (size_t)blockIdx.x * C * C;
    int i0 = ti * 8, j0 = tj * 8;
#pragma unroll
    for (int a = 0; a < 8; a++) {
        float4 o0 = make_float4(r[a][0], r[a][1], r[a][2], r[a][3]);
        float4 o1 = make_float4(r[a][4], r[a][5], r[a][6], r[a][7]);
        float4* op = (float4*)(out + (size_t)(i0 + a) * C + j0);
        op[0] = o0; op[1] = o1;
    }
}

// ---------------- fused attn-numer + GCN + blend + acc (128 nodes / block) ----------------
__global__ __launch_bounds__(256) void k_update(int flip, int N) {
    extern __shared__ float sm[];
    float* Ms = sm;                 // [128][132]
    float* qs = Ms + 128 * 132;     // [8][128]
    float* vs = qs + 8 * C;         // [128]
    const float* src = flip ? g_cur1 : g_cur0;
    float* dst = flip ? g_cur0 : g_cur1;
    int tid = threadIdx.x;
    int nodeBase = blockIdx.x * 128;
    int b = g_batch[nodeBase];

    // sum 4 partial M's into padded smem
    const float* mp = g_Mp + (size_t)b * 4 * C * C;
    for (int idx = tid; idx < C * C; idx += 256) {
        float s = mp[idx] + mp[C * C + idx] + mp[2 * C * C + idx] + mp[3 * C * C + idx];
        int i = idx >> 7, j = idx & 127;
        Ms[i * 132 + j] = s;
    }
    if (tid < C) vs[tid] = g_vsum[b * C + tid];

    int c4 = tid & 31, mg = tid >> 5;
    for (int r = 0; r < 16; r++) {
        __syncthreads();
        for (int idx = tid; idx < 8 * C; idx += 256)
            qs[idx] = g_q[(size_t)(nodeBase + r * 8) * C + idx];
        __syncthreads();
        int m = nodeBase + r * 8 + mg;
        float4 a = ((const float4*)vs)[c4];
        const float* qrow = qs + mg * C;
#pragma unroll 4
        for (int i = 0; i < C; i++) {
            float4 w = *(const float4*)&Ms[i * 132 + c4 * 4];
            float qv = qrow[i];
            a.x = fmaf(qv, w.x, a.x);
            a.y = fmaf(qv, w.y, a.y);
            a.z = fmaf(qv, w.z, a.z);
            a.w = fmaf(qv, w.w, a.w);
        }
        float inv = 1.f / g_denom[m];
        a.x *= inv; a.y *= inv; a.z *= inv; a.w *= inv;

        float4 g = make_float4(0.f, 0.f, 0.f, 0.f);
        int p0 = g_rowptr[m], p1 = g_rowptr[m + 1];
        for (int p = p0; p < p1; p++) {
            int cc = g_ccol[p];
            float cf = g_ccoef[p];
            float4 xv = ((const float4*)(src + (size_t)cc * C))[c4];
            g.x = fmaf(cf, xv.x, g.x);
            g.y = fmaf(cf, xv.y, g.y);
            g.z = fmaf(cf, xv.z, g.z);
            g.w = fmaf(cf, xv.w, g.w);
        }
        float4 nw;
        nw.x = BETA * g.x + (1.f - BETA) * a.x;
        nw.y = BETA * g.y + (1.f - BETA) * a.y;
        nw.z = BETA * g.z + (1.f - BETA) * a.z;
        nw.w = BETA * g.w + (1.f - BETA) * a.w;
        ((float4*)(dst + (size_t)m * C))[c4] = nw;
        float4 ac = ((float4*)(g_acc + (size_t)m * C))[c4];
        ac.x += nw.x; ac.y += nw.y; ac.z += nw.z; ac.w += nw.w;
        ((float4*)(g_acc + (size_t)m * C))[c4] = ac;
    }
}

// ---------------- launch ----------------
extern "C" void kernel_launch(void* const* d_in, const int* in_sizes, int n_in,
                              void* d_out, int out_size) {
    const float* x    = (const float*)d_in[0];
    const int*   ei   = (const int*)d_in[1];
    const float* ew   = (const float*)d_in[2];
    const int*   nn   = (const int*)d_in[3];
    const float* Wq_w = (const float*)d_in[4];
    const float* Wq_b = (const float*)d_in[5];
    const float* Wk_w = (const float*)d_in[6];
    const float* Wk_b = (const float*)d_in[7];
    const float* Wo_w = (const float*)d_in[8];
    const float* Wo_b = (const float*)d_in[9];
    float* out = (float*)d_out;

    int N = in_sizes[0] / C;
    int E = in_sizes[2];
    int B = in_sizes[3];
    const int* row = ei;
    const int* col = ei + E;

    const int GEMM_SMEM = (128 * 132 + 64 * C + C) * 4;       // 100864
    const int UPD_SMEM  = (128 * 132 + 8 * C + C) * 4;        // 72192
    cudaFuncSetAttribute(k_gemm_bias, cudaFuncAttributeMaxDynamicSharedMemorySize, GEMM_SMEM);
    cudaFuncSetAttribute(k_update,    cudaFuncAttributeMaxDynamicSharedMemorySize, UPD_SMEM);

    k_zero<<<(N + 255) / 256, 256>>>(N);
    k_offsets<<<1, 32>>>(nn, B);
    k_batch<<<(N + 255) / 256, 256>>>(N, B);
    k_deg<<<(E + 255) / 256, 256>>>(row, ew, E);
    k_dinv<<<(N + 255) / 256, 256>>>(N);
    k_coef<<<(E + 255) / 256, 256>>>(row, col, ew, E);
    k_scan<<<1, 1024>>>(N);
    k_scatter<<<(E + 255) / 256, 256>>>(row, col, E);

    k_gemm_bias<<<N / 64, 256, GEMM_SMEM>>>(x, Wq_w, Wq_b, nullptr, 0, N);
    k_gemm_bias<<<N / 64, 256, GEMM_SMEM>>>(x, Wk_w, Wk_b, nullptr, 1, N);
    k_norm<<<(N + 7) / 8, 256>>>(0, N);
    k_norm<<<(N + 7) / 8, 256>>>(1, N);
    k_colsum<<<B, 128>>>(0, 0);                 // ksum (iteration-invariant)
    k_denom<<<(N + 7) / 8, 256>>>(N);           // denom (iteration-invariant)
    k_init<<<(N * C / 4 + 255) / 256, 256>>>(x, N * C / 4);

    int flip = 0;
    for (int it = 0; it < KORDER; it++) {
        k_colsum<<<B, 128>>>(1, flip);          // vsum from cur
        k_mbuild<<<B * 4, 256>>>(flip);         // partial K^T V
        k_update<<<N / 128, 256, UPD_SMEM>>>(flip, N);
        flip ^= 1;
    }

    k_gemm_bias<<<N / 64, 256, GEMM_SMEM>>>(nullptr, Wo_w, Wo_b, out, 2, N);
}

// round 2
// speedup vs baseline: 1.6449x; 1.6449x over previous
#include <cuda_runtime.h>

#define C 128
#define NMAX 32768
#define EMAX 524288
#define BMAX 64
#define KORDER 4
#define BETA 0.5f

// ---------------- scratch (static device memory, no allocation) ----------------
__device__ __align__(256) float g_q[NMAX * C];
__device__ __align__(256) float g_k[NMAX * C];
__device__ __align__(256) float g_cur0[NMAX * C];
__device__ __align__(256) float g_cur1[NMAX * C];
__device__ __align__(256) float g_acc[NMAX * C];
__device__ __align__(256) float g_deg[NMAX];
__device__ __align__(256) float g_dinv[NMAX];
__device__ __align__(256) float g_coef[EMAX];
__device__ __align__(256) int   g_cnt[NMAX];
__device__ __align__(256) int   g_rowptr[NMAX + 1];
__device__ __align__(256) int   g_fill[NMAX];
__device__ __align__(256) int   g_ccol[EMAX];
__device__ __align__(256) float g_ccoef[EMAX];
__device__ __align__(256) int   g_offsets[BMAX + 1];
__device__ __align__(256) int   g_batch[NMAX];
__device__ __align__(256) float g_Mp[BMAX * 4 * C * C];   // 4 partial K^T V per graph
__device__ __align__(256) float g_M[BMAX * C * C];        // reduced K^T V per graph
__device__ __align__(256) float g_ksum[BMAX * C];
__device__ __align__(256) float g_vsum[BMAX * C];
__device__ __align__(256) float g_denom[NMAX];

// ---------------- preprocessing ----------------
__global__ void k_zero(int N) {
    int i = blockIdx.x * blockDim.x + threadIdx.x;
    if (i < N) { g_deg[i] = 0.f; g_cnt[i] = 0; g_fill[i] = 0; }
}

__global__ void k_offsets(const int* __restrict__ nn, int B) {
    if (threadIdx.x == 0) {
        int run = 0;
        for (int b = 0; b < B; b++) { g_offsets[b] = run; run += nn[b]; }
        g_offsets[B] = run;
    }
}

__global__ void k_batch(int N, int B) {
    __shared__ int offs[BMAX + 1];
    for (int i = threadIdx.x; i <= B; i += blockDim.x) offs[i] = g_offsets[i];
    __syncthreads();
    int n = blockIdx.x * blockDim.x + threadIdx.x;
    if (n >= N) return;
    int lo = 0, hi = B - 1;
    while (lo < hi) {
        int mid = (lo + hi + 1) >> 1;
        if (offs[mid] <= n) lo = mid; else hi = mid - 1;
    }
    g_batch[n] = lo;
}

__global__ void k_deg(const int* __restrict__ row, const float* __restrict__ w, int E) {
    int e = blockIdx.x * blockDim.x + threadIdx.x;
    if (e < E) atomicAdd(&g_deg[row[e]], w[e]);
}

__global__ void k_dinv(int N) {
    int n = blockIdx.x * blockDim.x + threadIdx.x;
    if (n < N) {
        float d = g_deg[n];
        g_dinv[n] = (d > 0.f) ? (1.f / sqrtf(d)) : 0.f;
    }
}

__global__ void k_coef(const int* __restrict__ row, const int* __restrict__ col,
                       const float* __restrict__ w, int E) {
    int e = blockIdx.x * blockDim.x + threadIdx.x;
    if (e < E) {
        int r = row[e];
        g_coef[e] = g_dinv[r] * g_dinv[col[e]] * w[e];
        atomicAdd(&g_cnt[r], 1);
    }
}

__global__ void k_scan(int N) {
    __shared__ int sm[1024];
    int t = threadIdx.x;
    int per = (N + 1023) >> 10;
    int base = t * per;
    int s = 0;
    for (int i = 0; i < per; i++) { int idx = base + i; if (idx < N) s += g_cnt[idx]; }
    sm[t] = s;
    __syncthreads();
    for (int off = 1; off < 1024; off <<= 1) {
        int v = (t >= off) ? sm[t - off] : 0;
        __syncthreads();
        sm[t] += v;
        __syncthreads();
    }
    int run = (t == 0) ? 0 : sm[t - 1];
    for (int i = 0; i < per; i++) {
        int idx = base + i;
        if (idx < N) { g_rowptr[idx] = run; run += g_cnt[idx]; }
    }
    if (t == 1023) g_rowptr[N] = run;
}

__global__ void k_scatter(const int* __restrict__ row, const int* __restrict__ col, int E) {
    int e = blockIdx.x * blockDim.x + threadIdx.x;
    if (e < E) {
        int r = row[e];
        int p = g_rowptr[r] + atomicAdd(&g_fill[r], 1);
        g_ccol[p] = col[e];
        g_ccoef[p] = g_coef[e];
    }
}

// ---------------- dense GEMM: out[m][c] = sum_i A[m][i] * W[c][i] + bias[c] ----------------
__global__ __launch_bounds__(256) void k_gemm_bias(
    const float* __restrict__ Ain, const float* __restrict__ W,
    const float* __restrict__ bias, float* __restrict__ Oout, int mode, int N)
{
    extern __shared__ float sm[];
    float* Wt = sm;                  // [128][132] transposed W
    float* Xs = Wt + 128 * 132;      // [64][128]
    float* bs = Xs + 64 * C;         // [128]
    const float* A = (mode == 2) ? g_acc : Ain;
    float* out = (mode == 0) ? g_q : ((mode == 1) ? g_k : Oout);
    int tid = threadIdx.x;
    for (int idx = tid; idx < C * C; idx += 256) {
        int c = idx >> 7, i = idx & 127;
        Wt[i * 132 + c] = W[idx];
    }
    if (tid < C) bs[tid] = bias[tid];
    int nb = blockIdx.x * 64;
    const float4* Ax = (const float4*)(A + (size_t)nb * C);
    float4* Xs4 = (float4*)Xs;
    for (int q = tid; q < 64 * C / 4; q += 256) Xs4[q] = Ax[q];
    __syncthreads();

    int c4 = tid & 31, mg = tid >> 5;
    float4 bl = ((const float4*)bs)[c4];
    float4 accv[8];
#pragma unroll
    for (int j = 0; j < 8; j++) accv[j] = bl;
    const float* xbase = Xs + mg * 8 * C;
#pragma unroll 2
    for (int i4 = 0; i4 < 32; i4++) {
        float4 xv[8];
#pragma unroll
        for (int j = 0; j < 8; j++) xv[j] = *(const float4*)&xbase[j * C + i4 * 4];
#pragma unroll
        for (int t = 0; t < 4; t++) {
            float4 w = *(const float4*)&Wt[(i4 * 4 + t) * 132 + c4 * 4];
#pragma unroll
            for (int j = 0; j < 8; j++) {
                float xs_ = (t == 0) ? xv[j].x : (t == 1) ? xv[j].y : (t == 2) ? xv[j].z : xv[j].w;
                accv[j].x = fmaf(xs_, w.x, accv[j].x);
                accv[j].y = fmaf(xs_, w.y, accv[j].y);
                accv[j].z = fmaf(xs_, w.z, accv[j].z);
                accv[j].w = fmaf(xs_, w.w, accv[j].w);
            }
        }
    }
#pragma unroll
    for (int j = 0; j < 8; j++) {
        int m = nb + mg * 8 + j;
        ((float4*)(out + (size_t)m * C))[c4] = accv[j];
    }
}

// ---------------- row L2-normalize (warp per node) ----------------
__global__ void k_norm(int sel, int N) {
    float* v = sel ? g_k : g_q;
    int w = (blockIdx.x * blockDim.x + threadIdx.x) >> 5;
    int lane = threadIdx.x & 31;
    if (w >= N) return;
    float4 x = ((const float4*)(v + (size_t)w * C))[lane];
    float s = x.x * x.x + x.y * x.y + x.z * x.z + x.w * x.w;
#pragma unroll
    for (int o = 16; o; o >>= 1) s += __shfl_xor_sync(0xffffffffu, s, o);
    float inv = 1.f / sqrtf(s);
    x.x *= inv; x.y *= inv; x.z *= inv; x.w *= inv;
    ((float4*)(v + (size_t)w * C))[lane] = x;
}

// ---------------- per-graph column sums: 256 threads/graph, float4 coalesced ----------------
__global__ __launch_bounds__(256) void k_colsum(int mode, int flip) {
    __shared__ float4 red[8][32];
    int b = blockIdx.x, t = threadIdx.x;
    const float* src = (mode == 0) ? g_k : (flip ? g_cur1 : g_cur0);
    float* out = (mode == 0) ? g_ksum : g_vsum;
    int s0 = g_offsets[b], s1 = g_offsets[b + 1];
    int c4 = t & 31, g = t >> 5;
    float4 s = make_float4(0.f, 0.f, 0.f, 0.f);
    for (int n = s0 + g; n < s1; n += 8) {
        float4 v = ((const float4*)(src + (size_t)n * C))[c4];
        s.x += v.x; s.y += v.y; s.z += v.z; s.w += v.w;
    }
    red[g][c4] = s;
    __syncthreads();
    if (t < 32) {
        float4 a = red[0][t];
#pragma unroll
        for (int gg = 1; gg < 8; gg++) {
            float4 v = red[gg][t];
            a.x += v.x; a.y += v.y; a.z += v.z; a.w += v.w;
        }
        ((float4*)(out + b * C))[t] = a;
    }
}

// ---------------- denom[n] = q[n]·ksum[b] + n_b ----------------
__global__ void k_denom(int N) {
    int w = (blockIdx.x * blockDim.x + threadIdx.x) >> 5;
    int lane = threadIdx.x & 31;
    if (w >= N) return;
    int b = g_batch[w];
    float4 q = ((const float4*)(g_q + (size_t)w * C))[lane];
    float4 kk = ((const float4*)(g_ksum + b * C))[lane];
    float s = q.x * kk.x + q.y * kk.y + q.z * kk.z + q.w * kk.w;
#pragma unroll
    for (int o = 16; o; o >>= 1) s += __shfl_xor_sync(0xffffffffu, s, o);
    if (lane == 0) g_denom[w] = s + (float)(g_offsets[b + 1] - g_offsets[b]);
}

__global__ void k_init(const float* __restrict__ x, int total4) {
    int i = blockIdx.x * blockDim.x + threadIdx.x;
    if (i < total4) {
        float4 v = ((const float4*)x)[i];
        ((float4*)g_cur0)[i] = v;
        ((float4*)g_acc)[i] = v;
    }
}

// ---------------- M_b partial build: 4 blocks/graph, 16-node smem tiles ----------------
__global__ __launch_bounds__(256) void k_mbuild(int flip) {
    __shared__ __align__(16) float ks[16 * C];
    __shared__ __align__(16) float vs_[16 * C];
    const float* src = flip ? g_cur1 : g_cur0;
    int b = blockIdx.x >> 2, p = blockIdx.x & 3;
    int s0 = g_offsets[b], s1 = g_offsets[b + 1];
    int nb = s1 - s0;
    int chunk = (nb + 3) >> 2;
    int n0 = s0 + p * chunk;
    int n1 = min(n0 + chunk, s1);
    int tid = threadIdx.x;
    int ti = tid >> 4, tj = tid & 15;
    float r[8][8];
#pragma unroll
    for (int a = 0; a < 8; a++)
#pragma unroll
        for (int c = 0; c < 8; c++) r[a][c] = 0.f;

    float4* ks4 = (float4*)ks;
    float4* vs4 = (float4*)vs_;
    for (int base = n0; base < n1; base += 16) {
        __syncthreads();
        // cooperative load of 16 nodes of k and v (zero-pad past n1)
#pragma unroll
        for (int q = 0; q < 2; q++) {
            int f4 = tid + q * 256;          // 0..511 over [16][32] float4
            int node = base + (f4 >> 5);
            int cc = f4 & 31;
            float4 z = make_float4(0.f, 0.f, 0.f, 0.f);
            ks4[f4] = (node < n1) ? ((const float4*)(g_k + (size_t)node * C))[cc] : z;
            vs4[f4] = (node < n1) ? ((const float4*)(src + (size_t)node * C))[cc] : z;
        }
        __syncthreads();
#pragma unroll 4
        for (int nn = 0; nn < 16; nn++) {
            const float* kr = ks + nn * C;
            const float* vr = vs_ + nn * C;
            float4 k0 = ((const float4*)kr)[ti * 2];
            float4 k1 = ((const float4*)kr)[ti * 2 + 1];
            float4 v0 = ((const float4*)vr)[tj * 2];
            float4 v1 = ((const float4*)vr)[tj * 2 + 1];
            float ka[8] = {k0.x, k0.y, k0.z, k0.w, k1.x, k1.y, k1.z, k1.w};
            float va[8] = {v0.x, v0.y, v0.z, v0.w, v1.x, v1.y, v1.z, v1.w};
#pragma unroll
            for (int a = 0; a < 8; a++)
#pragma unroll
                for (int c = 0; c < 8; c++) r[a][c] = fmaf(ka[a], va[c], r[a][c]);
        }
    }
    float* out = g_Mp + (size_t)blockIdx.x * C * C;
    int i0 = ti * 8, j0 = tj * 8;
#pragma unroll
    for (int a = 0; a < 8; a++) {
        float4 o0 = make_float4(r[a][0], r[a][1], r[a][2], r[a][3]);
        float4 o1 = make_float4(r[a][4], r[a][5], r[a][6], r[a][7]);
        float4* op = (float4*)(out + (size_t)(i0 + a) * C + j0);
        op[0] = o0; op[1] = o1;
    }
}

// ---------------- reduce 4 M partials -> g_M ----------------
__global__ void k_msum(int B) {
    int i = blockIdx.x * blockDim.x + threadIdx.x;   // over B*C*C/4 float4
    int total = B * C * C / 4;
    if (i >= total) return;
    int b = i / (C * C / 4);
    int off = i - b * (C * C / 4);
    const float4* mp = (const float4*)(g_Mp + (size_t)b * 4 * C * C);
    float4 a = mp[off];
    float4 p1 = mp[C * C / 4 + off];
    float4 p2 = mp[2 * C * C / 4 + off];
    float4 p3 = mp[3 * C * C / 4 + off];
    a.x += p1.x + p2.x + p3.x;
    a.y += p1.y + p2.y + p3.y;
    a.z += p1.z + p2.z + p3.z;
    a.w += p1.w + p2.w + p3.w;
    ((float4*)(g_M + (size_t)b * C * C))[off] = a;
}

// ---------------- fused attn-numer + GCN + blend + acc (64 nodes/block, GEMM-style) ----------------
__global__ __launch_bounds__(256) void k_update(int flip, int N) {
    extern __shared__ float sm[];
    float* Ms = sm;                  // [128][132]
    float* qs = Ms + 128 * 132;      // [64][128]
    float* vs = qs + 64 * C;         // [128]
    const float* src = flip ? g_cur1 : g_cur0;
    float* dst = flip ? g_cur0 : g_cur1;
    int tid = threadIdx.x;
    int nodeBase = blockIdx.x * 64;
    int b = g_batch[nodeBase];

    const float* mg_ = g_M + (size_t)b * C * C;
    for (int idx = tid; idx < C * C; idx += 256) {
        int i = idx >> 7, j = idx & 127;
        Ms[i * 132 + j] = mg_[idx];
    }
    if (tid < C) vs[tid] = g_vsum[b * C + tid];
    {
        const float4* qsrc = (const float4*)(g_q + (size_t)nodeBase * C);
        float4* qd = (float4*)qs;
        for (int q = tid; q < 64 * C / 4; q += 256) qd[q] = qsrc[q];
    }
    __syncthreads();

    int c4 = tid & 31, mg = tid >> 5;
    float4 vinit = ((const float4*)vs)[c4];
    float4 accv[8];
#pragma unroll
    for (int j = 0; j < 8; j++) accv[j] = vinit;
    const float* qbase = qs + mg * 8 * C;
#pragma unroll 2
    for (int i4 = 0; i4 < 32; i4++) {
        float4 qv[8];
#pragma unroll
        for (int j = 0; j < 8; j++) qv[j] = *(const float4*)&qbase[j * C + i4 * 4];
#pragma unroll
        for (int t = 0; t < 4; t++) {
            float4 w = *(const float4*)&Ms[(i4 * 4 + t) * 132 + c4 * 4];
#pragma unroll
            for (int j = 0; j < 8; j++) {
                float qsc = (t == 0) ? qv[j].x : (t == 1) ? qv[j].y : (t == 2) ? qv[j].z : qv[j].w;
                accv[j].x = fmaf(qsc, w.x, accv[j].x);
                accv[j].y = fmaf(qsc, w.y, accv[j].y);
                accv[j].z = fmaf(qsc, w.z, accv[j].z);
                accv[j].w = fmaf(qsc, w.w, accv[j].w);
            }
        }
    }

    // epilogue: per node scale by 1/denom, add GCN gather, blend, store + acc
#pragma unroll 1
    for (int j = 0; j < 8; j++) {
        int m = nodeBase + mg * 8 + j;
        float inv = 1.f / g_denom[m];
        float4 a = accv[j];
        a.x *= inv; a.y *= inv; a.z *= inv; a.w *= inv;

        float4 g = make_float4(0.f, 0.f, 0.f, 0.f);
        int p0 = g_rowptr[m], p1 = g_rowptr[m + 1];
        for (int p = p0; p < p1; p++) {
            int cc = __ldg(&g_ccol[p]);
            float cf = __ldg(&g_ccoef[p]);
            float4 xv = ((const float4*)(src + (size_t)cc * C))[c4];
            g.x = fmaf(cf, xv.x, g.x);
            g.y = fmaf(cf, xv.y, g.y);
            g.z = fmaf(cf, xv.z, g.z);
            g.w = fmaf(cf, xv.w, g.w);
        }
        float4 nw;
        nw.x = BETA * g.x + (1.f - BETA) * a.x;
        nw.y = BETA * g.y + (1.f - BETA) * a.y;
        nw.z = BETA * g.z + (1.f - BETA) * a.z;
        nw.w = BETA * g.w + (1.f - BETA) * a.w;
        ((float4*)(dst + (size_t)m * C))[c4] = nw;
        float4 ac = ((float4*)(g_acc + (size_t)m * C))[c4];
        ac.x += nw.x; ac.y += nw.y; ac.z += nw.z; ac.w += nw.w;
        ((float4*)(g_acc + (size_t)m * C))[c4] = ac;
    }
}

// ---------------- launch ----------------
extern "C" void kernel_launch(void* const* d_in, const int* in_sizes, int n_in,
                              void* d_out, int out_size) {
    const float* x    = (const float*)d_in[0];
    const int*   ei   = (const int*)d_in[1];
    const float* ew   = (const float*)d_in[2];
    const int*   nn   = (const int*)d_in[3];
    const float* Wq_w = (const float*)d_in[4];
    const float* Wq_b = (const float*)d_in[5];
    const float* Wk_w = (const float*)d_in[6];
    const float* Wk_b = (const float*)d_in[7];
    const float* Wo_w = (const float*)d_in[8];
    const float* Wo_b = (const float*)d_in[9];
    float* out = (float*)d_out;

    int N = in_sizes[0] / C;
    int E = in_sizes[2];
    int B = in_sizes[3];
    const int* row = ei;
    const int* col = ei + E;

    const int GEMM_SMEM = (128 * 132 + 64 * C + C) * 4;       // ~100.8KB
    const int UPD_SMEM  = (128 * 132 + 64 * C + C) * 4;
    cudaFuncSetAttribute(k_gemm_bias, cudaFuncAttributeMaxDynamicSharedMemorySize, GEMM_SMEM);
    cudaFuncSetAttribute(k_update,    cudaFuncAttributeMaxDynamicSharedMemorySize, UPD_SMEM);

    k_zero<<<(N + 255) / 256, 256>>>(N);
    k_offsets<<<1, 32>>>(nn, B);
    k_batch<<<(N + 255) / 256, 256>>>(N, B);
    k_deg<<<(E + 255) / 256, 256>>>(row, ew, E);
    k_dinv<<<(N + 255) / 256, 256>>>(N);
    k_coef<<<(E + 255) / 256, 256>>>(row, col, ew, E);
    k_scan<<<1, 1024>>>(N);
    k_scatter<<<(E + 255) / 256, 256>>>(row, col, E);

    k_gemm_bias<<<N / 64, 256, GEMM_SMEM>>>(x, Wq_w, Wq_b, nullptr, 0, N);
    k_gemm_bias<<<N / 64, 256, GEMM_SMEM>>>(x, Wk_w, Wk_b, nullptr, 1, N);
    k_norm<<<(N + 7) / 8, 256>>>(0, N);
    k_norm<<<(N + 7) / 8, 256>>>(1, N);
    k_colsum<<<B, 256>>>(0, 0);                 // ksum (iteration-invariant)
    k_denom<<<(N + 7) / 8, 256>>>(N);           // denom (iteration-invariant)
    k_init<<<(N * C / 4 + 255) / 256, 256>>>(x, N * C / 4);

    int msumBlocks = (B * C * C / 4 + 255) / 256;
    int flip = 0;
    for (int it = 0; it < KORDER; it++) {
        k_colsum<<<B, 256>>>(1, flip);          // vsum from cur
        k_mbuild<<<B * 4, 256>>>(flip);         // partial K^T V
        k_msum<<<msumBlocks, 256>>>(B);         // reduce partials once
        k_update<<<N / 64, 256, UPD_SMEM>>>(flip, N);
        flip ^= 1;
    }

    k_gemm_bias<<<N / 64, 256, GEMM_SMEM>>>(nullptr, Wo_w, Wo_b, out, 2, N);
}